// round 7
// baseline (speedup 1.0000x reference)
#include <cuda_runtime.h>
#include <math.h>
#include <stdint.h>

#define IMG_SIZE 255.0f
#define MAXB 64
#define MAXA 65536
#define CAP   65536
#define CHUNK 4096

// ---------------- device scratch (zeroed at load; K2's final block re-zeroes) ----
__device__ unsigned g_key[(size_t)MAXB * MAXA];   // 16 MB keys (L2-resident)
__device__ unsigned g_cand[MAXB][CAP];            // boundary-bin candidates
__device__ int      g_hist[MAXB][256];
__device__ int      g_rowpos[MAXB];
__device__ int      g_ncand[MAXB];
__device__ int      g_ticket[MAXB];
__device__ int      g_rowdone;
// floats: 0 loss_loc_sum, 1 pos_nll_sum, 2 pos_err_sum, 3 size_x, 4 size_y, 5 neg_nll_sel
__device__ float    g_f[8];
// ints:   0 N, 1 pos_correct, 2 neg_selected_total, 3 neg_correct
__device__ int      g_i[4];

__device__ __forceinline__ float smooth_l1(float x) {
    float ax = fabsf(x);
    return (ax < 1.0f) ? 0.5f * x * x : ax - 0.5f;
}
__device__ __forceinline__ float softplus(float d) {   // nll at target 0
    return fmaxf(d, 0.0f) + log1pf(expf(-fabsf(d)));
}
__device__ __forceinline__ unsigned f2ord(float f) {
    unsigned u = __float_as_uint(f);
    return (u & 0x80000000u) ? ~u : (u | 0x80000000u);
}
__device__ __forceinline__ float ord2f(unsigned k) {
    unsigned u = (k & 0x80000000u) ? (k & 0x7FFFFFFFu) : ~k;
    return __uint_as_float(u);
}

// orderable key (0 unless label==0); IEEE division keeps labels bit-identical
__device__ __forceinline__ unsigned make_key(float4 g, float areaA, float4 pr,
                                             float d, bool* pos) {
    float ax0 = pr.x - pr.z * 0.5f, ay0 = pr.y - pr.w * 0.5f;
    float ax1 = pr.x + pr.z * 0.5f, ay1 = pr.y + pr.w * 0.5f;
    float iw = fmaxf(fminf(g.z, ax1) - fmaxf(g.x, ax0), 0.0f);
    float ih = fmaxf(fminf(g.w, ay1) - fmaxf(g.y, ay0), 0.0f);
    float inter = iw * ih;
    float iou = inter / (areaA + (ax1 - ax0) * (ay1 - ay0) - inter);
    *pos = (iou >= 0.6f);
    return (iou <= 0.3f) ? f2ord(d) : 0u;
}

__device__ __noinline__ void pos_work(const float* __restrict__ loc,
                                      float4 g, float4 pr, float d,
                                      size_t idx, int b) {
    atomicAdd(&g_rowpos[b], 1);
    atomicAdd(&g_i[0], 1);
    atomicAdd(&g_f[1], softplus(-d));                 // nll at target 1
    if (d > 0.0f) atomicAdd(&g_i[1], 1);
    const float* lp = loc + idx * 4;
    float l0 = lp[0], l1 = lp[1], l2 = lp[2], l3 = lp[3];
    float gw = g.z - g.x, gh = g.w - g.y;
    float gcx = (g.x + g.z) * 0.5f, gcy = (g.y + g.w) * 0.5f;
    float e0 = (gcx - pr.x) / (0.1f * pr.z);
    float e1 = (gcy - pr.y) / (0.1f * pr.w);
    float e2 = logf(gw / pr.z) / 0.2f;
    float e3 = logf(gh / pr.w) / 0.2f;
    atomicAdd(&g_f[0], smooth_l1(l0 - e0) + smooth_l1(l1 - e1) +
                       smooth_l1(l2 - e2) + smooth_l1(l3 - e3));
    float dcx = pr.x + l0 * 0.1f * pr.z;
    float dcy = pr.y + l1 * 0.1f * pr.w;
    float dw  = pr.z * expf(l2 * 0.2f);
    float dh  = pr.w * expf(l3 * 0.2f);
    float dx0 = dcx - dw * 0.5f, dy0 = dcy - dh * 0.5f;
    float ex = (g.x - dx0) * IMG_SIZE, ey = (g.y - dy0) * IMG_SIZE;
    atomicAdd(&g_f[2], sqrtf(ex * ex + ey * ey));
    atomicAdd(&g_f[3], fabsf(g.z - (dx0 + dw)));
    atomicAdd(&g_f[4], fabsf(g.w - (dy0 + dh)));
}

// parallel cutoff over 256-bin histogram in shared s (destroyed); blockDim=256
__device__ __forceinline__ void suffix_cutoff(int* s, int k, int* out_c, int* out_kk) {
    int t = threadIdx.x;
    #pragma unroll
    for (int off = 1; off < 256; off <<= 1) {
        int add = (t + off < 256) ? s[t + off] : 0;
        __syncthreads();
        s[t] += add;
        __syncthreads();
    }
    __shared__ int sc, skk;
    if (t == 0) { sc = 0; skk = k; }
    __syncthreads();
    int St = s[t];
    int Sn = (t < 255) ? s[t + 1] : 0;
    if (Sn < k && k <= St) { sc = t; skk = k - Sn; }
    __syncthreads();
    *out_c = sc; *out_kk = skk;
}

__device__ __forceinline__ void warp_hist_add(int* sh, unsigned bin) {
    unsigned m = __match_any_sync(0xffffffffu, bin);
    if ((threadIdx.x & 31) == (unsigned)(__ffs(m) - 1)) atomicAdd(&sh[bin], __popc(m));
}

// ---------------- K1: keys once + histogram + sparse positive work ----------------
__global__ void __launch_bounds__(256) k_pass1(
        const float*  __restrict__ loc,
        const float4* __restrict__ conf4,   // conf as pairs of float2
        const float4* __restrict__ gt4,
        const float4* __restrict__ anch,
        int A) {
    int b = blockIdx.y;
    int t = threadIdx.x;
    size_t rowoff = (size_t)b * A;
    __shared__ int sh[256];
    sh[t] = 0;
    __syncthreads();

    float4 g = gt4[b];
    float areaA = (g.z - g.x) * (g.w - g.y);
    int base = blockIdx.x * CHUNK;

    #pragma unroll
    for (int it = 0; it < CHUNK / 1024; ++it) {       // 4 iters, 4 elems/thread
        int a0 = base + (it * 256 + t) * 4;
        size_t cbase = (rowoff + (size_t)a0) >> 1;
        float4 cA = conf4[cbase];
        float4 cB = conf4[cbase + 1];
        float4 p0 = anch[a0], p1 = anch[a0 + 1], p2 = anch[a0 + 2], p3 = anch[a0 + 3];
        float d0 = cA.y - cA.x, d1 = cA.w - cA.z;
        float d2 = cB.y - cB.x, d3 = cB.w - cB.z;
        bool q0, q1, q2, q3;
        unsigned k0 = make_key(g, areaA, p0, d0, &q0);
        unsigned k1 = make_key(g, areaA, p1, d1, &q1);
        unsigned k2 = make_key(g, areaA, p2, d2, &q2);
        unsigned k3 = make_key(g, areaA, p3, d3, &q3);
        reinterpret_cast<uint4*>(g_key + rowoff)[(size_t)a0 >> 2] =
            make_uint4(k0, k1, k2, k3);
        warp_hist_add(sh, k0 >> 24);
        warp_hist_add(sh, k1 >> 24);
        warp_hist_add(sh, k2 >> 24);
        warp_hist_add(sh, k3 >> 24);
        if (q0) pos_work(loc, g, p0, d0, rowoff + a0, b);
        if (q1) pos_work(loc, g, p1, d1, rowoff + a0 + 1, b);
        if (q2) pos_work(loc, g, p2, d2, rowoff + a0 + 2, b);
        if (q3) pos_work(loc, g, p3, d3, rowoff + a0 + 3, b);
    }
    __syncthreads();
    if (sh[t]) atomicAdd(&g_hist[b][t], sh[t]);
}

// ---------------- K2: parallel selection sweep + per-row drill + finalize ----------
__global__ void __launch_bounds__(256) k_pass2(
        float* __restrict__ out, int out_size, int A, int B) {
    int b = blockIdx.y;
    int t = threadIdx.x;
    size_t rowoff = (size_t)b * A;
    __shared__ int sh[256];
    __shared__ float s_sum;
    __shared__ int s_corr, s_last, s_fin;

    int np = g_rowpos[b];
    int k = 3 * np; if (k < 10) k = 10; if (k > A - 1) k = A - 1;
    sh[t] = g_hist[b][t];
    if (t == 0) { s_sum = 0.0f; s_corr = 0; }
    __syncthreads();
    int c1, kk1;
    suffix_cutoff(sh, k, &c1, &kk1);
    unsigned c1u = (unsigned)c1;

    // scan this block's own 4096 keys: 4 unrolled uint4 loads per thread (L2)
    const uint4* kp = reinterpret_cast<const uint4*>(g_key + rowoff)
                      + blockIdx.x * (CHUNK / 4);
    float lsum = 0.0f; int lcorr = 0;
    #pragma unroll
    for (int it = 0; it < CHUNK / 1024; ++it) {
        uint4 u4 = __ldcg(&kp[it * 256 + t]);
        unsigned uu[4] = {u4.x, u4.y, u4.z, u4.w};
        #pragma unroll
        for (int j = 0; j < 4; ++j) {
            unsigned u = uu[j];
            unsigned bin = u >> 24;
            if (bin > c1u) {
                lsum += softplus(ord2f(u));
                if (u <= 0x80000000u) lcorr++;         // d <= 0 -> pred==0
            }
            bool isCand = (bin == c1u);
            unsigned m = __ballot_sync(0xffffffffu, isCand);
            if (m) {
                int lane = t & 31;
                int basep = 0;
                if (lane == (__ffs(m) - 1))
                    basep = atomicAdd(&g_ncand[b], __popc(m));
                basep = __shfl_sync(0xffffffffu, basep, __ffs(m) - 1);
                if (isCand) {
                    int p = basep + __popc(m & ((1u << lane) - 1));
                    if (p < CAP) g_cand[b][p] = u;
                }
            }
        }
    }
    #pragma unroll
    for (int o = 16; o > 0; o >>= 1) {
        lsum  += __shfl_down_sync(0xffffffffu, lsum, o);
        lcorr += __shfl_down_sync(0xffffffffu, lcorr, o);
    }
    if ((t & 31) == 0) { atomicAdd(&s_sum, lsum); atomicAdd(&s_corr, lcorr); }
    __syncthreads();
    if (t == 0) {
        if (s_sum != 0.0f) atomicAdd(&g_f[5], s_sum);
        if (s_corr)        atomicAdd(&g_i[3], s_corr);
        __threadfence();                               // release candidates+sums
        s_last = (atomicAdd(&g_ticket[b], 1) == (int)gridDim.x - 1);
    }
    __syncthreads();
    if (!s_last) return;

    // ---- last block of row: drill bytes 2/1/0 within boundary bin ----
    __threadfence();                                   // acquire peers' writes
    int n = __ldcg(&g_ncand[b]); if (n > CAP) n = CAP;

    sh[t] = 0;
    __syncthreads();
    for (int i = t; i < n; i += 256)
        atomicAdd(&sh[(__ldcg(&g_cand[b][i]) >> 16) & 0xFFu], 1);
    __syncthreads();
    int c2, kk2;
    suffix_cutoff(sh, kk1, &c2, &kk2);

    sh[t] = 0;
    __syncthreads();
    for (int i = t; i < n; i += 256) {
        unsigned u = __ldcg(&g_cand[b][i]);
        if (((u >> 16) & 0xFFu) == (unsigned)c2) atomicAdd(&sh[(u >> 8) & 0xFFu], 1);
    }
    __syncthreads();
    int c3, kk3;
    suffix_cutoff(sh, kk2, &c3, &kk3);

    sh[t] = 0;
    __syncthreads();
    for (int i = t; i < n; i += 256) {
        unsigned u = __ldcg(&g_cand[b][i]);
        if (((u >> 16) & 0xFFu) == (unsigned)c2 && ((u >> 8) & 0xFFu) == (unsigned)c3)
            atomicAdd(&sh[u & 0xFFu], 1);
    }
    __syncthreads();
    int c4, kkf;
    suffix_cutoff(sh, kk3, &c4, &kkf);

    unsigned v = (c1u << 24) | ((unsigned)c2 << 16) | ((unsigned)c3 << 8) | (unsigned)c4;

    float rsum = 0.0f; int rcorr = 0;
    for (int i = t; i < n; i += 256) {
        unsigned u = __ldcg(&g_cand[b][i]);
        if (u > v) {
            rsum += softplus(ord2f(u));
            if (u <= 0x80000000u) rcorr++;
        }
    }
    #pragma unroll
    for (int o = 16; o > 0; o >>= 1) {
        rsum  += __shfl_down_sync(0xffffffffu, rsum, o);
        rcorr += __shfl_down_sync(0xffffffffu, rcorr, o);
    }
    if (t == 0) { s_sum = 0.0f; s_corr = 0; }
    __syncthreads();
    if ((t & 31) == 0) { atomicAdd(&s_sum, rsum); atomicAdd(&s_corr, rcorr); }
    __syncthreads();
    if (t == 0) {
        float dv = ord2f(v);
        float tie_nll = (kkf > 0) ? (float)kkf * softplus(dv) : 0.0f;
        int   tie_cor = (kkf > 0 && v <= 0x80000000u) ? kkf : 0;
        atomicAdd(&g_f[5], s_sum + tie_nll);
        atomicAdd(&g_i[3], s_corr + tie_cor);
        atomicAdd(&g_i[2], k);
        __threadfence();
        s_fin = (atomicAdd(&g_rowdone, 1) == B - 1);
    }
    __syncthreads();
    if (!s_fin) return;

    // ---- globally last block: finalize + reset scratch for next replay ----
    __threadfence();
    if (t == 0) {
        float Nf0 = (float)__ldcg(&g_i[0]);
        float Nf = fmaxf(Nf0, 1.0f);
        float loss_loc = __ldcg(&g_f[0]) / (Nf * 4.0f);
        float wsum = Nf0 + (float)__ldcg(&g_i[2]) * (1.0f / 3.0f);
        float loss_cls = (__ldcg(&g_f[1]) + __ldcg(&g_f[5]) * (1.0f / 3.0f)) / wsum;
        float pos_acc = (float)__ldcg(&g_i[1]) / fmaxf((float)__ldcg(&g_i[0]), 1.0f);
        float neg_acc = (float)__ldcg(&g_i[3]) / fmaxf((float)__ldcg(&g_i[2]), 1.0f);
        float vals[8] = {loss_loc, loss_cls, pos_acc, neg_acc,
                         __ldcg(&g_f[2]) / Nf,
                         __ldcg(&g_f[3]) / Nf * IMG_SIZE,
                         __ldcg(&g_f[4]) / Nf * IMG_SIZE, Nf0};
        for (int i = 0; i < 8 && i < out_size; i++) out[i] = vals[i];
    }
    for (int i = t; i < MAXB * 256; i += 256) ((int*)g_hist)[i] = 0;
    if (t < MAXB) { g_rowpos[t] = 0; g_ncand[t] = 0; g_ticket[t] = 0; }
    if (t < 8) g_f[t] = 0.0f;
    if (t < 4) g_i[t] = 0;
    if (t == 0) g_rowdone = 0;
}

// ---------------- launch ----------------
extern "C" void kernel_launch(void* const* d_in, const int* in_sizes, int n_in,
                              void* d_out, int out_size) {
    const float*  loc     = (const float*)d_in[0];
    const float4* conf4   = (const float4*)d_in[1];
    const float4* gt      = (const float4*)d_in[2];
    const float4* anchors = (const float4*)d_in[3];
    int B = in_sizes[2] / 4;
    int A = in_sizes[3] / 4;
    if (B > MAXB) B = MAXB;
    if (A > MAXA) A = MAXA;

    int bpr = (A + CHUNK - 1) / CHUNK;   // 16 for A=65536
    k_pass1<<<dim3(bpr, B), 256>>>(loc, conf4, gt, anchors, A);
    k_pass2<<<dim3(bpr, B), 256>>>((float*)d_out, out_size, A, B);
}

// round 8
// speedup vs baseline: 2.0111x; 2.0111x over previous
#include <cuda_runtime.h>
#include <math.h>
#include <stdint.h>

#define IMG_SIZE 255.0f
#define MAXB 64
#define MAXA 65536
#define CAP   65536
#define CHUNK 4096
#define SBUF  4096   // per-block smem candidate buffer (block scans CHUNK keys)

// ---------------- device scratch (zeroed at load; final block re-zeroes) ----------
__device__ unsigned g_key[(size_t)MAXB * MAXA];   // 16 MB keys
__device__ unsigned g_cand[MAXB][CAP];            // boundary-bin candidates
__device__ int      g_hist [MAXB][256];           // byte-3 histogram
__device__ int      g_hist2[MAXB][256];           // byte-2 histogram of candidates
__device__ int      g_rowpos[MAXB];
__device__ int      g_ncand[MAXB];
__device__ int      g_ticket[MAXB];
__device__ int      g_rowdone;
// floats: 0 loss_loc_sum, 1 pos_nll_sum, 2 pos_err_sum, 3 size_x, 4 size_y, 5 neg_nll_sel
__device__ float    g_f[8];
// ints:   0 N, 1 pos_correct, 2 neg_selected_total, 3 neg_correct
__device__ int      g_i[4];

__device__ __forceinline__ float smooth_l1(float x) {
    float ax = fabsf(x);
    return (ax < 1.0f) ? 0.5f * x * x : ax - 0.5f;
}
__device__ __forceinline__ float softplus(float d) {   // nll at target 0
    return fmaxf(d, 0.0f) + log1pf(expf(-fabsf(d)));
}
__device__ __forceinline__ unsigned f2ord(float f) {
    unsigned u = __float_as_uint(f);
    return (u & 0x80000000u) ? ~u : (u | 0x80000000u);
}
__device__ __forceinline__ float ord2f(unsigned k) {
    unsigned u = (k & 0x80000000u) ? (k & 0x7FFFFFFFu) : ~k;
    return __uint_as_float(u);
}

__device__ __forceinline__ unsigned make_key(float4 g, float areaA, float4 pr,
                                             float d, bool* pos) {
    float ax0 = pr.x - pr.z * 0.5f, ay0 = pr.y - pr.w * 0.5f;
    float ax1 = pr.x + pr.z * 0.5f, ay1 = pr.y + pr.w * 0.5f;
    float iw = fmaxf(fminf(g.z, ax1) - fmaxf(g.x, ax0), 0.0f);
    float ih = fmaxf(fminf(g.w, ay1) - fmaxf(g.y, ay0), 0.0f);
    float inter = iw * ih;
    float iou = inter / (areaA + (ax1 - ax0) * (ay1 - ay0) - inter);
    *pos = (iou >= 0.6f);
    return (iou <= 0.3f) ? f2ord(d) : 0u;
}

__device__ __noinline__ void pos_work(const float* __restrict__ loc,
                                      float4 g, float4 pr, float d,
                                      size_t idx, int b) {
    atomicAdd(&g_rowpos[b], 1);
    atomicAdd(&g_i[0], 1);
    atomicAdd(&g_f[1], softplus(-d));
    if (d > 0.0f) atomicAdd(&g_i[1], 1);
    const float* lp = loc + idx * 4;
    float l0 = lp[0], l1 = lp[1], l2 = lp[2], l3 = lp[3];
    float gw = g.z - g.x, gh = g.w - g.y;
    float gcx = (g.x + g.z) * 0.5f, gcy = (g.y + g.w) * 0.5f;
    float e0 = (gcx - pr.x) / (0.1f * pr.z);
    float e1 = (gcy - pr.y) / (0.1f * pr.w);
    float e2 = logf(gw / pr.z) / 0.2f;
    float e3 = logf(gh / pr.w) / 0.2f;
    atomicAdd(&g_f[0], smooth_l1(l0 - e0) + smooth_l1(l1 - e1) +
                       smooth_l1(l2 - e2) + smooth_l1(l3 - e3));
    float dcx = pr.x + l0 * 0.1f * pr.z;
    float dcy = pr.y + l1 * 0.1f * pr.w;
    float dw  = pr.z * expf(l2 * 0.2f);
    float dh  = pr.w * expf(l3 * 0.2f);
    float dx0 = dcx - dw * 0.5f, dy0 = dcy - dh * 0.5f;
    float ex = (g.x - dx0) * IMG_SIZE, ey = (g.y - dy0) * IMG_SIZE;
    atomicAdd(&g_f[2], sqrtf(ex * ex + ey * ey));
    atomicAdd(&g_f[3], fabsf(g.z - (dx0 + dw)));
    atomicAdd(&g_f[4], fabsf(g.w - (dy0 + dh)));
}

// parallel cutoff over 256-bin histogram in shared s (destroyed); blockDim=256
__device__ __forceinline__ void suffix_cutoff(int* s, int k, int* out_c, int* out_kk) {
    int t = threadIdx.x;
    #pragma unroll
    for (int off = 1; off < 256; off <<= 1) {
        int add = (t + off < 256) ? s[t + off] : 0;
        __syncthreads();
        s[t] += add;
        __syncthreads();
    }
    __shared__ int sc, skk;
    if (t == 0) { sc = 0; skk = k; }
    __syncthreads();
    int St = s[t];
    int Sn = (t < 255) ? s[t + 1] : 0;
    if (Sn < k && k <= St) { sc = t; skk = k - Sn; }
    __syncthreads();
    *out_c = sc; *out_kk = skk;
}

__device__ __forceinline__ void warp_hist_add(int* sh, unsigned bin) {
    unsigned m = __match_any_sync(0xffffffffu, bin);
    if ((threadIdx.x & 31) == (unsigned)(__ffs(m) - 1)) atomicAdd(&sh[bin], __popc(m));
}

// ---------------- K1: keys once + histogram + sparse positive work ----------------
__global__ void __launch_bounds__(256) k_pass1(
        const float*  __restrict__ loc,
        const float4* __restrict__ conf4,
        const float4* __restrict__ gt4,
        const float4* __restrict__ anch,
        int A) {
    int b = blockIdx.y;
    int t = threadIdx.x;
    size_t rowoff = (size_t)b * A;
    __shared__ int sh[256];
    sh[t] = 0;
    __syncthreads();

    float4 g = gt4[b];
    float areaA = (g.z - g.x) * (g.w - g.y);
    int base = blockIdx.x * CHUNK;

    #pragma unroll
    for (int it = 0; it < CHUNK / 1024; ++it) {
        int a0 = base + (it * 256 + t) * 4;
        size_t cbase = (rowoff + (size_t)a0) >> 1;
        float4 cA = conf4[cbase];
        float4 cB = conf4[cbase + 1];
        float4 p0 = anch[a0], p1 = anch[a0 + 1], p2 = anch[a0 + 2], p3 = anch[a0 + 3];
        float d0 = cA.y - cA.x, d1 = cA.w - cA.z;
        float d2 = cB.y - cB.x, d3 = cB.w - cB.z;
        bool q0, q1, q2, q3;
        unsigned k0 = make_key(g, areaA, p0, d0, &q0);
        unsigned k1 = make_key(g, areaA, p1, d1, &q1);
        unsigned k2 = make_key(g, areaA, p2, d2, &q2);
        unsigned k3 = make_key(g, areaA, p3, d3, &q3);
        reinterpret_cast<uint4*>(g_key + rowoff)[(size_t)a0 >> 2] =
            make_uint4(k0, k1, k2, k3);
        warp_hist_add(sh, k0 >> 24);
        warp_hist_add(sh, k1 >> 24);
        warp_hist_add(sh, k2 >> 24);
        warp_hist_add(sh, k3 >> 24);
        if (q0) pos_work(loc, g, p0, d0, rowoff + a0, b);
        if (q1) pos_work(loc, g, p1, d1, rowoff + a0 + 1, b);
        if (q2) pos_work(loc, g, p2, d2, rowoff + a0 + 2, b);
        if (q3) pos_work(loc, g, p3, d3, rowoff + a0 + 3, b);
    }
    __syncthreads();
    if (sh[t]) atomicAdd(&g_hist[b][t], sh[t]);
}

// ---------------- K2: sweep with smem candidate staging + per-row tail ----------
__global__ void __launch_bounds__(256) k_pass2(
        float* __restrict__ out, int out_size, int A, int B) {
    int b = blockIdx.y;
    int t = threadIdx.x;
    size_t rowoff = (size_t)b * A;
    __shared__ unsigned s_cand[SBUF];   // 16 KB
    __shared__ int sh[256];
    __shared__ float s_sum;
    __shared__ int s_corr, s_last, s_fin, s_n;

    int np = g_rowpos[b];
    int k = 3 * np; if (k < 10) k = 10; if (k > A - 1) k = A - 1;
    sh[t] = g_hist[b][t];
    if (t == 0) { s_sum = 0.0f; s_corr = 0; s_n = 0; }
    __syncthreads();
    int c1, kk1;
    suffix_cutoff(sh, k, &c1, &kk1);
    unsigned c1u = (unsigned)c1;

    // ---- sweep this block's 4096 keys; candidates -> SMEM (no global atomics) ----
    const uint4* kp = reinterpret_cast<const uint4*>(g_key + rowoff)
                      + blockIdx.x * (CHUNK / 4);
    float lsum = 0.0f; int lcorr = 0;
    #pragma unroll
    for (int it = 0; it < CHUNK / 1024; ++it) {
        uint4 u4 = __ldcg(&kp[it * 256 + t]);
        unsigned uu[4] = {u4.x, u4.y, u4.z, u4.w};
        #pragma unroll
        for (int j = 0; j < 4; ++j) {
            unsigned u = uu[j];
            unsigned bin = u >> 24;
            if (bin > c1u) {
                lsum += softplus(ord2f(u));
                if (u <= 0x80000000u) lcorr++;
            }
            bool isCand = (bin == c1u);
            unsigned m = __ballot_sync(0xffffffffu, isCand);
            if (m) {
                int lane = t & 31;
                int basep = 0;
                if (lane == (__ffs(m) - 1))
                    basep = atomicAdd(&s_n, __popc(m));        // SHARED atomic
                basep = __shfl_sync(0xffffffffu, basep, __ffs(m) - 1);
                if (isCand) s_cand[basep + __popc(m & ((1u << lane) - 1))] = u;
            }
        }
    }
    #pragma unroll
    for (int o = 16; o > 0; o >>= 1) {
        lsum  += __shfl_down_sync(0xffffffffu, lsum, o);
        lcorr += __shfl_down_sync(0xffffffffu, lcorr, o);
    }
    if ((t & 31) == 0) { atomicAdd(&s_sum, lsum); atomicAdd(&s_corr, lcorr); }
    __syncthreads();

    // block-local byte-2 histogram of candidates, then flush everything once
    int bn = s_n;
    sh[t] = 0;
    __syncthreads();
    for (int i = t; i < bn; i += 256)
        atomicAdd(&sh[(s_cand[i] >> 16) & 0xFFu], 1);
    __syncthreads();
    __shared__ int s_base;
    if (t == 0) {
        if (s_sum != 0.0f) atomicAdd(&g_f[5], s_sum);
        if (s_corr)        atomicAdd(&g_i[3], s_corr);
        s_base = bn ? atomicAdd(&g_ncand[b], bn) : 0;          // ONE global atomic
    }
    __syncthreads();
    int gbase = s_base;
    for (int i = t; i < bn; i += 256) {
        int p = gbase + i;
        if (p < CAP) g_cand[b][p] = s_cand[i];
    }
    if (sh[t]) atomicAdd(&g_hist2[b][t], sh[t]);
    __threadfence();
    if (t == 0) s_last = (atomicAdd(&g_ticket[b], 1) == (int)gridDim.x - 1);
    __syncthreads();
    if (!s_last) return;

    // ---- last block of row: drill bytes 2/1/0 ----
    __threadfence();
    int n = __ldcg(&g_ncand[b]); if (n > CAP) n = CAP;

    sh[t] = __ldcg(&g_hist2[b][t]);
    __syncthreads();
    int c2, kk2;
    suffix_cutoff(sh, kk1, &c2, &kk2);

    // single pass over candidates: sum byte2 > c2, stage byte2 == c2 into smem
    if (t == 0) { s_sum = 0.0f; s_corr = 0; s_n = 0; }
    __syncthreads();
    float rsum = 0.0f; int rcorr = 0;
    for (int i = t; i < n; i += 256) {
        unsigned u = __ldcg(&g_cand[b][i]);
        unsigned b2 = (u >> 16) & 0xFFu;
        if (b2 > (unsigned)c2) {
            rsum += softplus(ord2f(u));
            if (u <= 0x80000000u) rcorr++;
        } else if (b2 == (unsigned)c2) {
            int p = atomicAdd(&s_n, 1);
            if (p < SBUF) s_cand[p] = u;
        }
    }
    #pragma unroll
    for (int o = 16; o > 0; o >>= 1) {
        rsum  += __shfl_down_sync(0xffffffffu, rsum, o);
        rcorr += __shfl_down_sync(0xffffffffu, rcorr, o);
    }
    if ((t & 31) == 0) { atomicAdd(&s_sum, rsum); atomicAdd(&s_corr, rcorr); }
    __syncthreads();
    int m2 = s_n;
    bool in_smem = (m2 <= SBUF);
    int msub = in_smem ? m2 : 0;

    // byte 1 cutoff
    sh[t] = 0;
    __syncthreads();
    if (in_smem) {
        for (int i = t; i < msub; i += 256)
            atomicAdd(&sh[(s_cand[i] >> 8) & 0xFFu], 1);
    } else {
        for (int i = t; i < n; i += 256) {
            unsigned u = __ldcg(&g_cand[b][i]);
            if (((u >> 16) & 0xFFu) == (unsigned)c2)
                atomicAdd(&sh[(u >> 8) & 0xFFu], 1);
        }
    }
    __syncthreads();
    int c3, kk3;
    suffix_cutoff(sh, kk2, &c3, &kk3);

    // byte 0 cutoff
    sh[t] = 0;
    __syncthreads();
    if (in_smem) {
        for (int i = t; i < msub; i += 256) {
            unsigned u = s_cand[i];
            if (((u >> 8) & 0xFFu) == (unsigned)c3) atomicAdd(&sh[u & 0xFFu], 1);
        }
    } else {
        for (int i = t; i < n; i += 256) {
            unsigned u = __ldcg(&g_cand[b][i]);
            if (((u >> 16) & 0xFFu) == (unsigned)c2 && ((u >> 8) & 0xFFu) == (unsigned)c3)
                atomicAdd(&sh[u & 0xFFu], 1);
        }
    }
    __syncthreads();
    int c4, kkf;
    suffix_cutoff(sh, kk3, &c4, &kkf);

    unsigned v = (c1u << 24) | ((unsigned)c2 << 16) | ((unsigned)c3 << 8) | (unsigned)c4;
    unsigned vlow = v & 0xFFFFu;

    // final: among byte2==c2 subset, sum keys with low16 > vlow
    float fsum = 0.0f; int fcorr = 0;
    if (in_smem) {
        for (int i = t; i < msub; i += 256) {
            unsigned u = s_cand[i];
            if ((u & 0xFFFFu) > vlow) {
                fsum += softplus(ord2f(u));
                if (u <= 0x80000000u) fcorr++;
            }
        }
    } else {
        for (int i = t; i < n; i += 256) {
            unsigned u = __ldcg(&g_cand[b][i]);
            if (u > v && ((u >> 16) & 0xFFu) == (unsigned)c2) {
                fsum += softplus(ord2f(u));
                if (u <= 0x80000000u) fcorr++;
            }
        }
    }
    #pragma unroll
    for (int o = 16; o > 0; o >>= 1) {
        fsum  += __shfl_down_sync(0xffffffffu, fsum, o);
        fcorr += __shfl_down_sync(0xffffffffu, fcorr, o);
    }
    if ((t & 31) == 0) { atomicAdd(&s_sum, fsum); atomicAdd(&s_corr, fcorr); }
    __syncthreads();
    if (t == 0) {
        float dv = ord2f(v);
        float tie_nll = (kkf > 0) ? (float)kkf * softplus(dv) : 0.0f;
        int   tie_cor = (kkf > 0 && v <= 0x80000000u) ? kkf : 0;
        atomicAdd(&g_f[5], s_sum + tie_nll);
        atomicAdd(&g_i[3], s_corr + tie_cor);
        atomicAdd(&g_i[2], k);
        __threadfence();
        s_fin = (atomicAdd(&g_rowdone, 1) == B - 1);
    }
    __syncthreads();
    if (!s_fin) return;

    // ---- globally last block: finalize + reset scratch ----
    __threadfence();
    if (t == 0) {
        float Nf0 = (float)__ldcg(&g_i[0]);
        float Nf = fmaxf(Nf0, 1.0f);
        float loss_loc = __ldcg(&g_f[0]) / (Nf * 4.0f);
        float wsum = Nf0 + (float)__ldcg(&g_i[2]) * (1.0f / 3.0f);
        float loss_cls = (__ldcg(&g_f[1]) + __ldcg(&g_f[5]) * (1.0f / 3.0f)) / wsum;
        float pos_acc = (float)__ldcg(&g_i[1]) / fmaxf((float)__ldcg(&g_i[0]), 1.0f);
        float neg_acc = (float)__ldcg(&g_i[3]) / fmaxf((float)__ldcg(&g_i[2]), 1.0f);
        float vals[8] = {loss_loc, loss_cls, pos_acc, neg_acc,
                         __ldcg(&g_f[2]) / Nf,
                         __ldcg(&g_f[3]) / Nf * IMG_SIZE,
                         __ldcg(&g_f[4]) / Nf * IMG_SIZE, Nf0};
        for (int i = 0; i < 8 && i < out_size; i++) out[i] = vals[i];
    }
    for (int i = t; i < MAXB * 256; i += 256) {
        ((int*)g_hist)[i] = 0;
        ((int*)g_hist2)[i] = 0;
    }
    if (t < MAXB) { g_rowpos[t] = 0; g_ncand[t] = 0; g_ticket[t] = 0; }
    if (t < 8) g_f[t] = 0.0f;
    if (t < 4) g_i[t] = 0;
    if (t == 0) g_rowdone = 0;
}

// ---------------- launch ----------------
extern "C" void kernel_launch(void* const* d_in, const int* in_sizes, int n_in,
                              void* d_out, int out_size) {
    const float*  loc     = (const float*)d_in[0];
    const float4* conf4   = (const float4*)d_in[1];
    const float4* gt      = (const float4*)d_in[2];
    const float4* anchors = (const float4*)d_in[3];
    int B = in_sizes[2] / 4;
    int A = in_sizes[3] / 4;
    if (B > MAXB) B = MAXB;
    if (A > MAXA) A = MAXA;

    int bpr = (A + CHUNK - 1) / CHUNK;   // 16 for A=65536
    k_pass1<<<dim3(bpr, B), 256>>>(loc, conf4, gt, anchors, A);
    k_pass2<<<dim3(bpr, B), 256>>>((float*)d_out, out_size, A, B);
}